// round 1
// baseline (speedup 1.0000x reference)
#include <cuda_runtime.h>
#include <cstdint>
#include <cstddef>

#define NROWS 200000
#define DIMX 256
#define HID 128
#define NSEG 512

// ---------------- scratch (no allocations allowed) ----------------
__device__ float g_scores[NROWS];
__device__ int g_seg[NSEG + 1];

// ---------------- small PTX helpers ----------------
__device__ __forceinline__ void ffma2(unsigned long long &d, unsigned long long a,
                                      unsigned long long b) {
    // packed 2x fp32 FMA (FFMA2) — only reachable via PTX f32x2
    asm("fma.rn.f32x2 %0, %1, %2, %0;" : "+l"(d) : "l"(a), "l"(b));
}
__device__ __forceinline__ unsigned long long dup2(float x) {
    unsigned long long r;
    asm("mov.b64 %0, {%1, %2};" : "=l"(r) : "f"(x), "f"(x));
    return r;
}
__device__ __forceinline__ float2 unpk(unsigned long long v) {
    float2 r;
    asm("mov.b64 {%0, %1}, %2;" : "=f"(r.x), "=f"(r.y) : "l"(v));
    return r;
}
__device__ __forceinline__ void cp16(void *smem_dst, const void *gsrc) {
    uint32_t s = (uint32_t)__cvta_generic_to_shared(smem_dst);
    asm volatile("cp.async.cg.shared.global [%0], [%1], 16;" ::"r"(s), "l"(gsrc));
}
__device__ __forceinline__ void cp_commit() {
    asm volatile("cp.async.commit_group;");
}
template <int N>
__device__ __forceinline__ void cp_wait() {
    asm volatile("cp.async.wait_group %0;" ::"n"(N));
}

// ---------------- scores kernel ----------------
// Persistent blocks. W1 (128 KB) staged in smem once per block.
// x streamed in double-buffered 32 KB k-chunks (128 rows x 64 k) via cp.async.
// Thread tile: 8 rows x 8 cols, accumulators as packed f32x2 (FFMA2).
constexpr int TILE_R = 128;
constexpr int KC = 64;
constexpr int NKC = DIMX / KC;  // 4
constexpr int TPB = 256;
constexpr int NTILES = (NROWS + TILE_R - 1) / TILE_R;  // 1563
constexpr int GRID_SCORES = 152;                        // GB300: 152 SMs
constexpr int SMEM_W = DIMX * HID;                      // 32768 floats (128 KB)
constexpr int SMEM_XBUF = TILE_R * KC;                  // 8192 floats (32 KB)
constexpr size_t SMEM_BYTES = (size_t)(SMEM_W + 2 * SMEM_XBUF) * 4;  // 196608 B

__global__ void __launch_bounds__(TPB, 1)
scores_kernel(const float *__restrict__ x, const float *__restrict__ W1,
              const float *__restrict__ b1, const float *__restrict__ W2,
              const float *__restrict__ b2) {
    extern __shared__ float smem[];
    float *W1s = smem;                 // [256][128] row-major (k-major)
    float *xs0 = smem + SMEM_W;        // 2 x [128][64]

    const int tid = threadIdx.x;
    const int cc = tid & 15;   // 16 col-threads: cols {4cc..4cc+3, 64+4cc..64+4cc+3}
    const int rg = tid >> 4;   // 16 row groups x 8 rows = 128 rows

    // Stage W1 into smem (once per persistent block)
    {
        float4 *d4 = (float4 *)W1s;
        const float4 *s4 = (const float4 *)W1;
        for (int i = tid; i < SMEM_W / 4; i += TPB) d4[i] = s4[i];
    }
    // per-thread column constants
    const float4 b1a = *(const float4 *)(b1 + 4 * cc);
    const float4 b1b = *(const float4 *)(b1 + 64 + 4 * cc);
    const float4 w2a = *(const float4 *)(W2 + 4 * cc);
    const float4 w2b = *(const float4 *)(W2 + 64 + 4 * cc);
    const float b2v = *b2;
    __syncthreads();

    const ulonglong2 *wp = (const ulonglong2 *)W1s;  // row k: 32 ull2

    for (int tile = blockIdx.x; tile < NTILES; tile += GRID_SCORES) {
        const int r0 = tile * TILE_R;

        // async chunk loader: 2048 x 16B per chunk
        auto load_chunk = [&](int kc, int b) {
            float *dst = xs0 + b * SMEM_XBUF;
            const float *src = x + (size_t)r0 * DIMX + kc * KC;
            #pragma unroll
            for (int it = 0; it < (TILE_R * KC / 4) / TPB; it++) {
                int i = tid + it * TPB;
                int row = i >> 4;
                int c16 = i & 15;
                if (r0 + row < NROWS)
                    cp16(dst + row * KC + c16 * 4, src + (size_t)row * DIMX + c16 * 4);
            }
            cp_commit();
        };

        unsigned long long acc[8][4];
        #pragma unroll
        for (int r = 0; r < 8; r++)
            #pragma unroll
            for (int j = 0; j < 4; j++) acc[r][j] = 0ull;

        load_chunk(0, 0);
        for (int kc = 0; kc < NKC; kc++) {
            __syncthreads();  // all consumers of buf (kc+1)&1 are done
            if (kc + 1 < NKC) {
                load_chunk(kc + 1, (kc + 1) & 1);
                cp_wait<1>();  // chunk kc complete, kc+1 may be in flight
            } else {
                cp_wait<0>();
            }
            __syncthreads();  // chunk kc visible to all threads

            const float4 *xb4 = (const float4 *)(xs0 + (kc & 1) * SMEM_XBUF);
            #pragma unroll 1
            for (int k4 = 0; k4 < KC / 4; k4++) {
                float4 xv[8];
                #pragma unroll
                for (int r = 0; r < 8; r++)
                    xv[r] = xb4[(rg * 8 + r) * (KC / 4) + k4];
                #pragma unroll
                for (int kk = 0; kk < 4; kk++) {
                    const int kg = kc * KC + k4 * 4 + kk;
                    ulonglong2 wA = wp[kg * 32 + cc];        // cols 4cc..4cc+3
                    ulonglong2 wB = wp[kg * 32 + 16 + cc];   // cols 64+4cc..
                    #pragma unroll
                    for (int r = 0; r < 8; r++) {
                        float xk = ((const float *)&xv[r])[kk];
                        unsigned long long xd = dup2(xk);
                        ffma2(acc[r][0], wA.x, xd);
                        ffma2(acc[r][1], wA.y, xd);
                        ffma2(acc[r][2], wB.x, xd);
                        ffma2(acc[r][3], wB.y, xd);
                    }
                }
            }
        }

        // epilogue: tanh -> dot with W2 -> reduce over 16 col-threads
        #pragma unroll
        for (int r = 0; r < 8; r++) {
            float2 v0 = unpk(acc[r][0]);
            float2 v1 = unpk(acc[r][1]);
            float2 v2 = unpk(acc[r][2]);
            float2 v3 = unpk(acc[r][3]);
            float p = tanhf(v0.x + b1a.x) * w2a.x + tanhf(v0.y + b1a.y) * w2a.y +
                      tanhf(v1.x + b1a.z) * w2a.z + tanhf(v1.y + b1a.w) * w2a.w +
                      tanhf(v2.x + b1b.x) * w2b.x + tanhf(v2.y + b1b.y) * w2b.y +
                      tanhf(v3.x + b1b.z) * w2b.z + tanhf(v3.y + b1b.w) * w2b.w;
            #pragma unroll
            for (int off = 8; off; off >>= 1)
                p += __shfl_xor_sync(0xffffffffu, p, off);
            if (cc == 0) {
                int row = r0 + rg * 8 + r;
                if (row < NROWS) g_scores[row] = p + b2v;
            }
        }
    }
}

// ---------------- segment boundaries (batch is sorted) ----------------
__global__ void seg_kernel(const int *__restrict__ batch) {
    int g = threadIdx.x;  // 512 threads
    int lo = 0, hi = NROWS;
    while (lo < hi) {
        int mid = (lo + hi) >> 1;
        if (batch[mid] < g) lo = mid + 1;
        else hi = mid;
    }
    g_seg[g] = lo;
    if (g == 0) g_seg[NSEG] = NROWS;
}

// ---------------- segment softmax + weighted pooling ----------------
__global__ void __launch_bounds__(256, 8)
pool_kernel(const float *__restrict__ x, float *__restrict__ out) {
    const int g = blockIdx.x;
    const int tid = threadIdx.x;
    __shared__ float red[8];
    __shared__ float bc;
    __shared__ float wbuf[256];

    const int s = g_seg[g];
    const int e = g_seg[g + 1];

    // pass 1: segment max
    float m = -3.4e38f;
    for (int i = s + tid; i < e; i += 256) m = fmaxf(m, g_scores[i]);
    #pragma unroll
    for (int off = 16; off; off >>= 1)
        m = fmaxf(m, __shfl_xor_sync(0xffffffffu, m, off));
    if ((tid & 31) == 0) red[tid >> 5] = m;
    __syncthreads();
    if (tid == 0) {
        float v = red[0];
        #pragma unroll
        for (int i = 1; i < 8; i++) v = fmaxf(v, red[i]);
        bc = v;
    }
    __syncthreads();
    m = bc;
    __syncthreads();

    // pass 2: denom = sum exp(score - max)
    float ssum = 0.f;
    for (int i = s + tid; i < e; i += 256) ssum += expf(g_scores[i] - m);
    #pragma unroll
    for (int off = 16; off; off >>= 1)
        ssum += __shfl_xor_sync(0xffffffffu, ssum, off);
    if ((tid & 31) == 0) red[tid >> 5] = ssum;
    __syncthreads();
    if (tid == 0) {
        float v = 0.f;
        #pragma unroll
        for (int i = 0; i < 8; i++) v += red[i];
        bc = v;
    }
    __syncthreads();
    const float denom = bc;
    const float inv = 1.0f / denom;  // e==s never uses it; e>s -> denom>0

    // pass 3: out[g][d] = sum_i w_i * x[i][d]   (tid == d, coalesced rows)
    float acc = 0.f;
    for (int base = s; base < e; base += 256) {
        const int cnt = min(256, e - base);
        __syncthreads();
        if (tid < cnt) wbuf[tid] = expf(g_scores[base + tid] - m) * inv;
        __syncthreads();
        #pragma unroll 4
        for (int j = 0; j < cnt; j++)
            acc += wbuf[j] * x[(size_t)(base + j) * DIMX + tid];
    }
    out[(size_t)g * DIMX + tid] = acc;
}

// ---------------- launch ----------------
extern "C" void kernel_launch(void *const *d_in, const int *in_sizes, int n_in,
                              void *d_out, int out_size) {
    (void)in_sizes; (void)n_in; (void)out_size;
    const float *x  = (const float *)d_in[0];
    const int *batch = (const int *)d_in[1];
    const float *W1 = (const float *)d_in[2];
    const float *b1 = (const float *)d_in[3];
    const float *W2 = (const float *)d_in[4];
    const float *b2 = (const float *)d_in[5];
    float *out = (float *)d_out;

    cudaFuncSetAttribute(scores_kernel, cudaFuncAttributeMaxDynamicSharedMemorySize,
                         (int)SMEM_BYTES);
    scores_kernel<<<GRID_SCORES, TPB, SMEM_BYTES>>>(x, W1, b1, W2, b2);
    seg_kernel<<<1, NSEG>>>(batch);
    pool_kernel<<<NSEG, 256>>>(x, out);
}

// round 3
// speedup vs baseline: 1.2417x; 1.2417x over previous
#include <cuda_runtime.h>
#include <cuda_bf16.h>
#include <cstdint>
#include <cstddef>

#define NROWS 200000
#define DIMX 256
#define HID 128
#define NSEG 512

constexpr int TILE_M = 128;
constexpr int NTILES = (NROWS + TILE_M - 1) / TILE_M;  // 1563
constexpr int TPB = 256;

#define NCHEB 28
#define NNODE 56

// ---- smem layout (bytes) ----
constexpr int SM_B1 = 0;          // float[128]
constexpr int SM_W2 = 512;        // float[128]
constexpr int SM_COEF = 1024;     // float[28]
constexpr int SM_SPART = 1152;    // float[128][4]
constexpr int SM_WHI = 4096;      // 4 panels x 16KB  (Wt hi, SW128)
constexpr int SM_WLO = SM_WHI + 65536;
constexpr int SM_A = SM_WLO + 65536;  // 2 bufs x 32KB (hi 16K + lo 16K)
constexpr int SMEM_TOTAL = SM_A + 65536;  // 200704

__device__ float g_scores[NROWS];
__device__ __nv_bfloat16 g_wt_hi[HID * DIMX];  // [n][k]
__device__ __nv_bfloat16 g_wt_lo[HID * DIMX];
__device__ float g_coef[NCHEB];

// ---------------- helpers ----------------
__device__ __forceinline__ uint32_t smem_u32(const void *p) {
    uint32_t a;
    asm("{ .reg .u64 t; cvta.to.shared.u64 t, %1; cvt.u32.u64 %0, t; }" : "=r"(a) : "l"(p));
    return a;
}
#define SWZ(off) ((uint32_t)(off) ^ ((((uint32_t)(off)) >> 3) & 0x70u))

__device__ __forceinline__ uint32_t packbf(float lo, float hi) {
    uint32_t r;
    asm("cvt.rn.bf16x2.f32 %0, %1, %2;" : "=r"(r) : "f"(hi), "f"(lo));
    return r;
}
__device__ __forceinline__ float lo_of(uint32_t p) { return __uint_as_float(p << 16); }
__device__ __forceinline__ float hi_of(uint32_t p) { return __uint_as_float(p & 0xffff0000u); }

__device__ __forceinline__ void ldsm4(uint32_t *r, uint32_t addr) {
    asm volatile("ldmatrix.sync.aligned.m8n8.x4.shared.b16 {%0,%1,%2,%3}, [%4];"
                 : "=r"(r[0]), "=r"(r[1]), "=r"(r[2]), "=r"(r[3]) : "r"(addr));
}
__device__ __forceinline__ void mma16816(float *d, const uint32_t *a, const uint32_t *b) {
    asm volatile("mma.sync.aligned.m16n8k16.row.col.f32.bf16.bf16.f32 "
                 "{%0,%1,%2,%3}, {%4,%5,%6,%7}, {%8,%9}, {%0,%1,%2,%3};"
                 : "+f"(d[0]), "+f"(d[1]), "+f"(d[2]), "+f"(d[3])
                 : "r"(a[0]), "r"(a[1]), "r"(a[2]), "r"(a[3]), "r"(b[0]), "r"(b[1]));
}

// ---------------- prep: W1 -> Wt bf16 hi/lo ----------------
__global__ void prep_w(const float *__restrict__ W1) {
    int i = blockIdx.x * 256 + threadIdx.x;  // 32768
    int k = i >> 7, n = i & 127;             // W1[k][n]
    float v = W1[i];
    __nv_bfloat16 h = __float2bfloat16(v);
    g_wt_hi[n * DIMX + k] = h;
    g_wt_lo[n * DIMX + k] = __float2bfloat16(v - __bfloat162float(h));
}

// ---------------- prep: Chebyshev->monomial coeffs of tanh(sqrt(t))/sqrt(t) ----------------
__global__ void prep_cheb() {
    __shared__ double cheb[NCHEB], mono[NCHEB];
    int t = threadIdx.x;  // 64 threads
    if (t < NCHEB) { cheb[t] = 0.0; mono[t] = 0.0; }
    __syncthreads();
    if (t < NNODE) {
        double th = 3.14159265358979323846 * (t + 0.5) / NNODE;
        double c1 = cos(th);
        double tt = 18.0 * (c1 + 1.0);
        double xx = sqrt(tt);
        double g = (xx < 1e-8) ? 1.0 : (tanh(xx) / xx);
        double w = 2.0 / NNODE;
        double Tm = 1.0, Tc = c1;
        atomicAdd(&cheb[0], g * w);
        for (int k = 1; k < NCHEB; k++) {
            atomicAdd(&cheb[k], g * Tc * w);
            double Tn = 2.0 * c1 * Tc - Tm;
            Tm = Tc; Tc = Tn;
        }
    }
    __syncthreads();
    if (t < NCHEB) {
        double ck = cheb[t] * ((t == 0) ? 0.5 : 1.0);
        if (t == 0) {
            atomicAdd(&mono[0], ck);
        } else {
            double fact[NCHEB];
            fact[0] = 1.0;
            for (int i = 1; i < NCHEB; i++) fact[i] = fact[i - 1] * i;
            for (int m = 0; 2 * m <= t; m++) {
                int p = t - 2 * m;
                double p2 = (p >= 1) ? (double)(1ull << (p - 1)) : 0.5;
                double cf = (double)t * fact[t - m - 1] / (fact[m] * fact[p]) * p2;
                if (m & 1) cf = -cf;
                atomicAdd(&mono[p], ck * cf);
            }
        }
    }
    __syncthreads();
    if (t < NCHEB) g_coef[t] = (float)mono[t];
}

// tanh via clamped monomial poly in s = x^2/18 - 1 (coeffs in regs)
__device__ __forceinline__ float ftanh(float x, const float *cf) {
    float xc = fminf(fmaxf(x, -6.0f), 6.0f);
    float s = fmaf(xc * xc, 0.05555555555555555f, -1.0f);
    float p = cf[NCHEB - 1];
    #pragma unroll
    for (int i = NCHEB - 2; i >= 0; i--) p = fmaf(p, s, cf[i]);
    return xc * p;
}

// ---------------- scores kernel ----------------
__global__ void __launch_bounds__(TPB, 1)
scores_kernel(const float *__restrict__ x, const float *__restrict__ b1,
              const float *__restrict__ W2) {
    extern __shared__ char smem[];
    const uint32_t sb = smem_u32(smem);
    const int tid = threadIdx.x;
    const int wid = tid >> 5, lane = tid & 31;
    const int mg = wid >> 2, ng = wid & 3;  // warp tile: rows 64*mg.., cols 32*ng..

    // stage b1/W2/coeffs
    if (tid < HID) {
        ((float *)(smem + SM_B1))[tid] = b1[tid];
        ((float *)(smem + SM_W2))[tid] = W2[tid];
    }
    if (tid < NCHEB) ((float *)(smem + SM_COEF))[tid] = g_coef[tid];
    // stage Wt hi/lo into SW128 panels: panel c holds k in [64c, 64c+64)
    for (int i = tid; i < HID * (DIMX / 4); i += TPB) {
        int n = i >> 6, k4 = i & 63;  // k = k4*4
        uint2 vh = *(const uint2 *)(g_wt_hi + n * DIMX + k4 * 4);
        uint2 vl = *(const uint2 *)(g_wt_lo + n * DIMX + k4 * 4);
        uint32_t off = SWZ(n * 128 + (k4 & 15) * 8) + (uint32_t)(k4 >> 4) * 16384u;
        *(uint2 *)(smem + SM_WHI + off) = vh;
        *(uint2 *)(smem + SM_WLO + off) = vl;
    }
    __syncthreads();

    const int c4 = tid & 15, rg = tid >> 4;
    float *spart = (float *)(smem + SM_SPART);
    const float *b1s = (const float *)(smem + SM_B1);
    const float *w2s = (const float *)(smem + SM_W2);

    for (int tile = blockIdx.x; tile < NTILES; tile += gridDim.x) {
        const size_t r0 = (size_t)tile * TILE_M;

        float acc[4][4][4];
        #pragma unroll
        for (int i = 0; i < 4; i++)
            #pragma unroll
            for (int j = 0; j < 4; j++)
                #pragma unroll
                for (int q = 0; q < 4; q++) acc[i][j][q] = 0.0f;

        // load + convert chunk 0
        float4 v[8];
        #pragma unroll
        for (int i = 0; i < 8; i++) {
            int row = i * 16 + rg;
            v[i] = make_float4(0.f, 0.f, 0.f, 0.f);
            if (r0 + row < NROWS) v[i] = ((const float4 *)x)[(r0 + row) * 64 + c4];
        }
        #pragma unroll
        for (int i = 0; i < 8; i++) {
            int row = i * 16 + rg;
            uint32_t h01 = packbf(v[i].x, v[i].y), h23 = packbf(v[i].z, v[i].w);
            uint32_t l01 = packbf(v[i].x - lo_of(h01), v[i].y - hi_of(h01));
            uint32_t l23 = packbf(v[i].z - lo_of(h23), v[i].w - hi_of(h23));
            uint32_t off = SWZ(row * 128 + c4 * 8);
            *(uint2 *)(smem + SM_A + off) = make_uint2(h01, h23);
            *(uint2 *)(smem + SM_A + 16384 + off) = make_uint2(l01, l23);
        }
        __syncthreads();

        #pragma unroll 1
        for (int ch = 0; ch < 4; ch++) {
            const int b = ch & 1;
            // prefetch next chunk
            if (ch < 3) {
                #pragma unroll
                for (int i = 0; i < 8; i++) {
                    int row = i * 16 + rg;
                    v[i] = make_float4(0.f, 0.f, 0.f, 0.f);
                    if (r0 + row < NROWS)
                        v[i] = ((const float4 *)x)[(r0 + row) * 64 + (ch + 1) * 16 + c4];
                }
            }
            // mma over chunk ch
            const uint32_t ahi_b = sb + SM_A + b * 32768u;
            const uint32_t alo_b = ahi_b + 16384u;
            const uint32_t whi_b = sb + SM_WHI + ch * 16384u;
            const uint32_t wlo_b = sb + SM_WLO + ch * 16384u;
            const int arow = mg * 64 + (lane & 15);
            const int akb = (lane >> 4) * 8;
            const int bn = ng * 32 + ((lane >> 4) & 1) * 8 + (lane & 7);
            const int bkb = ((lane >> 3) & 1) * 8;
            #pragma unroll
            for (int ks = 0; ks < 4; ks++) {
                uint32_t ah[4][4], al[4][4], bh[2][4], bl[2][4];
                #pragma unroll
                for (int mt = 0; mt < 4; mt++) {
                    uint32_t off = SWZ((arow + mt * 16) * 128 + (ks * 16 + akb) * 2);
                    ldsm4(ah[mt], ahi_b + off);
                    ldsm4(al[mt], alo_b + off);
                }
                #pragma unroll
                for (int nt2 = 0; nt2 < 2; nt2++) {
                    uint32_t off = SWZ((bn + nt2 * 16) * 128 + (ks * 16 + bkb) * 2);
                    ldsm4(bh[nt2], whi_b + off);
                    ldsm4(bl[nt2], wlo_b + off);
                }
                #pragma unroll
                for (int mt = 0; mt < 4; mt++)
                    #pragma unroll
                    for (int nt = 0; nt < 4; nt++) {
                        const uint32_t *bhp = &bh[nt >> 1][(nt & 1) * 2];
                        const uint32_t *blp = &bl[nt >> 1][(nt & 1) * 2];
                        mma16816(acc[mt][nt], ah[mt], bhp);
                        mma16816(acc[mt][nt], ah[mt], blp);
                        mma16816(acc[mt][nt], al[mt], bhp);
                    }
            }
            // store next chunk
            if (ch < 3) {
                const int nb = (ch + 1) & 1;
                #pragma unroll
                for (int i = 0; i < 8; i++) {
                    int row = i * 16 + rg;
                    uint32_t h01 = packbf(v[i].x, v[i].y), h23 = packbf(v[i].z, v[i].w);
                    uint32_t l01 = packbf(v[i].x - lo_of(h01), v[i].y - hi_of(h01));
                    uint32_t l23 = packbf(v[i].z - lo_of(h23), v[i].w - hi_of(h23));
                    uint32_t off = SWZ(row * 128 + c4 * 8);
                    *(uint2 *)(smem + SM_A + nb * 32768 + off) = make_uint2(h01, h23);
                    *(uint2 *)(smem + SM_A + nb * 32768 + 16384 + off) = make_uint2(l01, l23);
                }
            }
            __syncthreads();
        }

        // ---- epilogue: tanh poly + dot W2, per-warp partials ----
        {
            float cf[NCHEB];
            #pragma unroll
            for (int i = 0; i < NCHEB; i++) cf[i] = ((const float *)(smem + SM_COEF))[i];
            const int rin = lane >> 2, cpair = (lane & 3) * 2;
            #pragma unroll
            for (int mt = 0; mt < 4; mt++) {
                float p0 = 0.f, p1 = 0.f;
                #pragma unroll
                for (int nt = 0; nt < 4; nt++) {
                    int c0 = ng * 32 + nt * 8 + cpair;
                    float w2a = w2s[c0], w2b = w2s[c0 + 1];
                    float b1a = b1s[c0], b1b = b1s[c0 + 1];
                    p0 += ftanh(acc[mt][nt][0] + b1a, cf) * w2a +
                          ftanh(acc[mt][nt][1] + b1b, cf) * w2b;
                    p1 += ftanh(acc[mt][nt][2] + b1a, cf) * w2a +
                          ftanh(acc[mt][nt][3] + b1b, cf) * w2b;
                }
                p0 += __shfl_xor_sync(0xffffffffu, p0, 1);
                p0 += __shfl_xor_sync(0xffffffffu, p0, 2);
                p1 += __shfl_xor_sync(0xffffffffu, p1, 1);
                p1 += __shfl_xor_sync(0xffffffffu, p1, 2);
                if ((lane & 3) == 0) {
                    int r = mg * 64 + mt * 16 + rin;
                    spart[r * 4 + ng] = p0;
                    spart[(r + 8) * 4 + ng] = p1;
                }
            }
        }
        __syncthreads();
        if (tid < 128) {
            size_t row = r0 + tid;
            if (row < NROWS)
                g_scores[row] = spart[tid * 4] + spart[tid * 4 + 1] +
                                spart[tid * 4 + 2] + spart[tid * 4 + 3];
        }
        __syncthreads();
    }
}

// ---------------- softmax + weighted pooling ----------------
__device__ __forceinline__ int lbound(const int *__restrict__ b, int target) {
    int lo = 0, hi = NROWS;
    while (lo < hi) {
        int mid = (lo + hi) >> 1;
        if (b[mid] < target) lo = mid + 1;
        else hi = mid;
    }
    return lo;
}

__global__ void __launch_bounds__(256)
pool_kernel(const float *__restrict__ x, const int *__restrict__ batch,
            float *__restrict__ out) {
    const int g = blockIdx.x, tid = threadIdx.x;
    __shared__ int sse[2];
    __shared__ float red[8];
    __shared__ float bc;
    __shared__ float4 red4[256];

    if (tid == 0) sse[0] = lbound(batch, g);
    if (tid == 32) sse[1] = lbound(batch, g + 1);
    __syncthreads();
    const int s = sse[0], e = sse[1];

    // segment max
    float m = -3.4e38f;
    for (int i = s + tid; i < e; i += 256) m = fmaxf(m, g_scores[i]);
    #pragma unroll
    for (int off = 16; off; off >>= 1) m = fmaxf(m, __shfl_xor_sync(0xffffffffu, m, off));
    if ((tid & 31) == 0) red[tid >> 5] = m;
    __syncthreads();
    if (tid == 0) {
        float v = red[0];
        #pragma unroll
        for (int i = 1; i < 8; i++) v = fmaxf(v, red[i]);
        bc = v;
    }
    __syncthreads();
    m = bc;
    __syncthreads();

    // denom
    float ss = 0.f;
    for (int i = s + tid; i < e; i += 256) ss += expf(g_scores[i] - m);
    #pragma unroll
    for (int off = 16; off; off >>= 1) ss += __shfl_xor_sync(0xffffffffu, ss, off);
    if ((tid & 31) == 0) red[tid >> 5] = ss;
    __syncthreads();
    if (tid == 0) {
        float v = 0.f;
        #pragma unroll
        for (int i = 0; i < 8; i++) v += red[i];
        bc = v;
    }
    __syncthreads();
    const float inv = 1.0f / bc;

    // weights in place (block owns its segment)
    for (int i = s + tid; i < e; i += 256) g_scores[i] = expf(g_scores[i] - m) * inv;
    __syncthreads();

    // weighted sum: 4 row-groups x 64 col-threads (float4)
    const int rq = tid >> 6, cq = tid & 63;
    float4 acc = make_float4(0.f, 0.f, 0.f, 0.f);
    const float4 *x4 = (const float4 *)x;
    #pragma unroll 2
    for (int i = s + rq; i < e; i += 4) {
        const float wv = g_scores[i];
        const float4 xv = x4[(size_t)i * 64 + cq];
        acc.x += wv * xv.x; acc.y += wv * xv.y;
        acc.z += wv * xv.z; acc.w += wv * xv.w;
    }
    red4[tid] = acc;
    __syncthreads();
    if (rq == 0) {
        float4 a = red4[tid], b = red4[tid + 64], c = red4[tid + 128], d = red4[tid + 192];
        a.x += b.x + c.x + d.x; a.y += b.y + c.y + d.y;
        a.z += b.z + c.z + d.z; a.w += b.w + c.w + d.w;
        ((float4 *)out)[(size_t)g * 64 + cq] = a;
    }
}

// ---------------- launch ----------------
extern "C" void kernel_launch(void *const *d_in, const int *in_sizes, int n_in,
                              void *d_out, int out_size) {
    (void)in_sizes; (void)n_in; (void)out_size;
    const float *x = (const float *)d_in[0];
    const int *batch = (const int *)d_in[1];
    const float *W1 = (const float *)d_in[2];
    const float *b1 = (const float *)d_in[3];
    const float *W2 = (const float *)d_in[4];
    float *out = (float *)d_out;

    static int grid_s = 0;
    if (grid_s == 0) {
        int sm = 148;
        cudaDeviceGetAttribute(&sm, cudaDevAttrMultiProcessorCount, 0);
        grid_s = sm;
        cudaFuncSetAttribute(scores_kernel, cudaFuncAttributeMaxDynamicSharedMemorySize,
                             SMEM_TOTAL);
    }
    prep_w<<<HID * DIMX / 256, 256>>>(W1);
    prep_cheb<<<1, 64>>>();
    scores_kernel<<<grid_s, TPB, SMEM_TOTAL>>>(x, b1, W2);
    pool_kernel<<<NSEG, 256>>>(x, batch, out);
}

// round 4
// speedup vs baseline: 1.3262x; 1.0680x over previous
#include <cuda_runtime.h>
#include <cuda_bf16.h>
#include <cstdint>
#include <cstddef>

#define NROWS 200000
#define DIMX 256
#define HID 128
#define NSEG 512

constexpr int TILE_M = 128;
constexpr int NTILES = (NROWS + TILE_M - 1) / TILE_M;  // 1563
constexpr int TPB = 512;

#define NCHEB 16
#define NNODE 32
#define CLAMP 4.5f
#define RANGE_T (CLAMP * CLAMP)   // 20.25

// ---- smem layout (bytes) ----
constexpr int SM_B1 = 0;          // float[128]
constexpr int SM_W2 = 512;        // float[128]
constexpr int SM_COEF = 1024;     // float[16]
constexpr int SM_SPART = 1152;    // float[128][4]
constexpr int SM_WHI = 4096;      // 4 panels x 16KB  (Wt hi, SW128)
constexpr int SM_WLO = SM_WHI + 65536;
constexpr int SM_A = SM_WLO + 65536;  // 2 bufs x 32KB (hi 16K + lo 16K)
constexpr int SMEM_TOTAL = SM_A + 65536;  // 200704

__device__ float g_scores[NROWS];
__device__ int g_seg[NSEG + 1];
__device__ __nv_bfloat16 g_wt_hi[HID * DIMX];  // [n][k]
__device__ __nv_bfloat16 g_wt_lo[HID * DIMX];
__device__ float g_coef[NCHEB];

// ---------------- helpers ----------------
__device__ __forceinline__ uint32_t smem_u32(const void *p) {
    uint32_t a;
    asm("{ .reg .u64 t; cvta.to.shared.u64 t, %1; cvt.u32.u64 %0, t; }" : "=r"(a) : "l"(p));
    return a;
}
#define SWZ(off) ((uint32_t)(off) ^ ((((uint32_t)(off)) >> 3) & 0x70u))

__device__ __forceinline__ uint32_t packbf(float lo, float hi) {
    uint32_t r;
    asm("cvt.rn.bf16x2.f32 %0, %1, %2;" : "=r"(r) : "f"(hi), "f"(lo));
    return r;
}
__device__ __forceinline__ float lo_of(uint32_t p) { return __uint_as_float(p << 16); }
__device__ __forceinline__ float hi_of(uint32_t p) { return __uint_as_float(p & 0xffff0000u); }

__device__ __forceinline__ void ldsm4(uint32_t *r, uint32_t addr) {
    asm volatile("ldmatrix.sync.aligned.m8n8.x4.shared.b16 {%0,%1,%2,%3}, [%4];"
                 : "=r"(r[0]), "=r"(r[1]), "=r"(r[2]), "=r"(r[3]) : "r"(addr));
}
__device__ __forceinline__ void mma16816(float *d, const uint32_t *a, const uint32_t *b) {
    asm volatile("mma.sync.aligned.m16n8k16.row.col.f32.bf16.bf16.f32 "
                 "{%0,%1,%2,%3}, {%4,%5,%6,%7}, {%8,%9}, {%0,%1,%2,%3};"
                 : "+f"(d[0]), "+f"(d[1]), "+f"(d[2]), "+f"(d[3])
                 : "r"(a[0]), "r"(a[1]), "r"(a[2]), "r"(a[3]), "r"(b[0]), "r"(b[1]));
}

// ---------------- prep: W1 -> Wt bf16 hi/lo ----------------
__global__ void prep_w(const float *__restrict__ W1) {
    int i = blockIdx.x * 256 + threadIdx.x;  // 32768
    int k = i >> 7, n = i & 127;             // W1[k][n]
    float v = W1[i];
    __nv_bfloat16 h = __float2bfloat16(v);
    g_wt_hi[n * DIMX + k] = h;
    g_wt_lo[n * DIMX + k] = __float2bfloat16(v - __bfloat162float(h));
}

// ---------------- prep: Chebyshev->monomial coeffs of tanh(sqrt(t))/sqrt(t) on [0,RANGE_T] ----------------
__global__ void prep_cheb() {
    __shared__ double cheb[NCHEB], mono[NCHEB];
    int t = threadIdx.x;  // 64 threads
    if (t < NCHEB) { cheb[t] = 0.0; mono[t] = 0.0; }
    __syncthreads();
    if (t < NNODE) {
        double th = 3.14159265358979323846 * (t + 0.5) / NNODE;
        double c1 = cos(th);
        double tt = (double)RANGE_T * 0.5 * (c1 + 1.0);
        double xx = sqrt(tt);
        double g = (xx < 1e-8) ? 1.0 : (tanh(xx) / xx);
        double w = 2.0 / NNODE;
        double Tm = 1.0, Tc = c1;
        atomicAdd(&cheb[0], g * w);
        for (int k = 1; k < NCHEB; k++) {
            atomicAdd(&cheb[k], g * Tc * w);
            double Tn = 2.0 * c1 * Tc - Tm;
            Tm = Tc; Tc = Tn;
        }
    }
    __syncthreads();
    if (t < NCHEB) {
        double ck = cheb[t] * ((t == 0) ? 0.5 : 1.0);
        if (t == 0) {
            atomicAdd(&mono[0], ck);
        } else {
            double fact[NCHEB];
            fact[0] = 1.0;
            for (int i = 1; i < NCHEB; i++) fact[i] = fact[i - 1] * i;
            for (int m = 0; 2 * m <= t; m++) {
                int p = t - 2 * m;
                double p2 = (p >= 1) ? (double)(1ull << (p - 1)) : 0.5;
                double cf = (double)t * fact[t - m - 1] / (fact[m] * fact[p]) * p2;
                if (m & 1) cf = -cf;
                atomicAdd(&mono[p], ck * cf);
            }
        }
    }
    __syncthreads();
    if (t < NCHEB) g_coef[t] = (float)mono[t];
}

// tanh via clamped monomial poly in s = x^2*(2/RANGE_T) - 1 (coeffs in regs)
__device__ __forceinline__ float ftanh(float x, const float *cf) {
    float xc = fminf(fmaxf(x, -CLAMP), CLAMP);
    float s = fmaf(xc * xc, 2.0f / RANGE_T, -1.0f);
    float p = cf[NCHEB - 1];
    #pragma unroll
    for (int i = NCHEB - 2; i >= 0; i--) p = fmaf(p, s, cf[i]);
    return xc * p;
}

// ---------------- scores kernel: 512 threads, 16 warps, warp tile 32x32 ----------------
__global__ void __launch_bounds__(TPB, 1)
scores_kernel(const float *__restrict__ x, const float *__restrict__ b1,
              const float *__restrict__ W2) {
    extern __shared__ char smem[];
    const uint32_t sb = smem_u32(smem);
    const int tid = threadIdx.x;
    const int wid = tid >> 5, lane = tid & 31;
    const int mg = wid >> 2, ng = wid & 3;  // warp tile: rows 32*mg.., cols 32*ng..

    if (tid < HID) {
        ((float *)(smem + SM_B1))[tid] = b1[tid];
        ((float *)(smem + SM_W2))[tid] = W2[tid];
    }
    if (tid < NCHEB) ((float *)(smem + SM_COEF))[tid] = g_coef[tid];
    // stage Wt hi/lo into SW128 panels: panel c holds k in [64c, 64c+64)
    for (int i = tid; i < HID * (DIMX / 4); i += TPB) {
        int n = i >> 6, k4 = i & 63;
        uint2 vh = *(const uint2 *)(g_wt_hi + n * DIMX + k4 * 4);
        uint2 vl = *(const uint2 *)(g_wt_lo + n * DIMX + k4 * 4);
        uint32_t off = SWZ(n * 128 + (k4 & 15) * 8) + (uint32_t)(k4 >> 4) * 16384u;
        *(uint2 *)(smem + SM_WHI + off) = vh;
        *(uint2 *)(smem + SM_WLO + off) = vl;
    }
    __syncthreads();

    const int c4 = tid & 15, rg = tid >> 4;  // rg 0..31; rows rg + 32i
    float *spart = (float *)(smem + SM_SPART);
    const float *b1s = (const float *)(smem + SM_B1);
    const float *w2s = (const float *)(smem + SM_W2);

    const int arow = mg * 32 + (lane & 15);
    const int akb = (lane >> 4) * 8;
    const int bn = ng * 32 + ((lane >> 4) & 1) * 8 + (lane & 7);
    const int bkb = ((lane >> 3) & 1) * 8;

    for (int tile = blockIdx.x; tile < NTILES; tile += gridDim.x) {
        const size_t r0 = (size_t)tile * TILE_M;

        float acc[2][4][4];
        #pragma unroll
        for (int i = 0; i < 2; i++)
            #pragma unroll
            for (int j = 0; j < 4; j++)
                #pragma unroll
                for (int q = 0; q < 4; q++) acc[i][j][q] = 0.0f;

        // load + convert chunk 0
        float4 v[4];
        #pragma unroll
        for (int i = 0; i < 4; i++) {
            int row = i * 32 + rg;
            v[i] = make_float4(0.f, 0.f, 0.f, 0.f);
            if (r0 + row < NROWS) v[i] = ((const float4 *)x)[(r0 + row) * 64 + c4];
        }
        #pragma unroll
        for (int i = 0; i < 4; i++) {
            int row = i * 32 + rg;
            uint32_t h01 = packbf(v[i].x, v[i].y), h23 = packbf(v[i].z, v[i].w);
            uint32_t l01 = packbf(v[i].x - lo_of(h01), v[i].y - hi_of(h01));
            uint32_t l23 = packbf(v[i].z - lo_of(h23), v[i].w - hi_of(h23));
            uint32_t off = SWZ(row * 128 + c4 * 8);
            *(uint2 *)(smem + SM_A + off) = make_uint2(h01, h23);
            *(uint2 *)(smem + SM_A + 16384 + off) = make_uint2(l01, l23);
        }
        __syncthreads();

        #pragma unroll 1
        for (int ch = 0; ch < 4; ch++) {
            const int b = ch & 1;
            // prefetch next chunk (global -> regs)
            if (ch < 3) {
                #pragma unroll
                for (int i = 0; i < 4; i++) {
                    int row = i * 32 + rg;
                    v[i] = make_float4(0.f, 0.f, 0.f, 0.f);
                    if (r0 + row < NROWS)
                        v[i] = ((const float4 *)x)[(r0 + row) * 64 + (ch + 1) * 16 + c4];
                }
            }
            // mma over chunk ch
            const uint32_t ahi_b = sb + SM_A + b * 32768u;
            const uint32_t alo_b = ahi_b + 16384u;
            const uint32_t whi_b = sb + SM_WHI + ch * 16384u;
            const uint32_t wlo_b = sb + SM_WLO + ch * 16384u;
            #pragma unroll
            for (int ks = 0; ks < 4; ks++) {
                uint32_t ah[2][4], al[2][4], bh[2][4], bl[2][4];
                #pragma unroll
                for (int mt = 0; mt < 2; mt++) {
                    uint32_t off = SWZ((arow + mt * 16) * 128 + (ks * 16 + akb) * 2);
                    ldsm4(ah[mt], ahi_b + off);
                    ldsm4(al[mt], alo_b + off);
                }
                #pragma unroll
                for (int nt2 = 0; nt2 < 2; nt2++) {
                    uint32_t off = SWZ((bn + nt2 * 16) * 128 + (ks * 16 + bkb) * 2);
                    ldsm4(bh[nt2], whi_b + off);
                    ldsm4(bl[nt2], wlo_b + off);
                }
                #pragma unroll
                for (int mt = 0; mt < 2; mt++)
                    #pragma unroll
                    for (int nt = 0; nt < 4; nt++) {
                        const uint32_t *bhp = &bh[nt >> 1][(nt & 1) * 2];
                        const uint32_t *blp = &bl[nt >> 1][(nt & 1) * 2];
                        mma16816(acc[mt][nt], ah[mt], bhp);
                        mma16816(acc[mt][nt], ah[mt], blp);
                        mma16816(acc[mt][nt], al[mt], bhp);
                    }
            }
            // store next chunk (regs -> smem)
            if (ch < 3) {
                const int nb = (ch + 1) & 1;
                #pragma unroll
                for (int i = 0; i < 4; i++) {
                    int row = i * 32 + rg;
                    uint32_t h01 = packbf(v[i].x, v[i].y), h23 = packbf(v[i].z, v[i].w);
                    uint32_t l01 = packbf(v[i].x - lo_of(h01), v[i].y - hi_of(h01));
                    uint32_t l23 = packbf(v[i].z - lo_of(h23), v[i].w - hi_of(h23));
                    uint32_t off = SWZ(row * 128 + c4 * 8);
                    *(uint2 *)(smem + SM_A + nb * 32768 + off) = make_uint2(h01, h23);
                    *(uint2 *)(smem + SM_A + nb * 32768 + 16384 + off) = make_uint2(l01, l23);
                }
            }
            __syncthreads();
        }

        // ---- epilogue: tanh poly + dot W2 ----
        {
            float cf[NCHEB];
            #pragma unroll
            for (int i = 0; i < NCHEB; i++) cf[i] = ((const float *)(smem + SM_COEF))[i];
            const int rin = lane >> 2, cpair = (lane & 3) * 2;
            #pragma unroll
            for (int mt = 0; mt < 2; mt++) {
                float p0 = 0.f, p1 = 0.f;
                #pragma unroll
                for (int nt = 0; nt < 4; nt++) {
                    int c0 = ng * 32 + nt * 8 + cpair;
                    float w2a = w2s[c0], w2b = w2s[c0 + 1];
                    float b1a = b1s[c0], b1b = b1s[c0 + 1];
                    p0 += ftanh(acc[mt][nt][0] + b1a, cf) * w2a +
                          ftanh(acc[mt][nt][1] + b1b, cf) * w2b;
                    p1 += ftanh(acc[mt][nt][2] + b1a, cf) * w2a +
                          ftanh(acc[mt][nt][3] + b1b, cf) * w2b;
                }
                p0 += __shfl_xor_sync(0xffffffffu, p0, 1);
                p0 += __shfl_xor_sync(0xffffffffu, p0, 2);
                p1 += __shfl_xor_sync(0xffffffffu, p1, 1);
                p1 += __shfl_xor_sync(0xffffffffu, p1, 2);
                if ((lane & 3) == 0) {
                    int r = mg * 32 + mt * 16 + rin;
                    spart[r * 4 + ng] = p0;
                    spart[(r + 8) * 4 + ng] = p1;
                }
            }
        }
        __syncthreads();
        if (tid < 128) {
            size_t row = r0 + tid;
            if (row < NROWS)
                g_scores[row] = spart[tid * 4] + spart[tid * 4 + 1] +
                                spart[tid * 4 + 2] + spart[tid * 4 + 3];
        }
        __syncthreads();
    }
}

// ---------------- weights: per-segment softmax, publish g_seg, zero out ----------------
__device__ __forceinline__ int lbound(const int *__restrict__ b, int target) {
    int lo = 0, hi = NROWS;
    while (lo < hi) {
        int mid = (lo + hi) >> 1;
        if (b[mid] < target) lo = mid + 1;
        else hi = mid;
    }
    return lo;
}

__global__ void __launch_bounds__(256)
weights_kernel(const int *__restrict__ batch, float *__restrict__ out) {
    const int g = blockIdx.x, tid = threadIdx.x;
    __shared__ int sse[2];
    __shared__ float red[8];
    __shared__ float bc;

    if (tid == 0) sse[0] = lbound(batch, g);
    if (tid == 32) sse[1] = lbound(batch, g + 1);
    out[(size_t)g * DIMX + tid] = 0.0f;   // zero our output row (256 threads = 256 cols)
    __syncthreads();
    const int s = sse[0], e = sse[1];
    if (tid == 0) {
        g_seg[g] = s;
        if (g == NSEG - 1) g_seg[NSEG] = NROWS;
    }

    float m = -3.4e38f;
    for (int i = s + tid; i < e; i += 256) m = fmaxf(m, g_scores[i]);
    #pragma unroll
    for (int off = 16; off; off >>= 1) m = fmaxf(m, __shfl_xor_sync(0xffffffffu, m, off));
    if ((tid & 31) == 0) red[tid >> 5] = m;
    __syncthreads();
    if (tid == 0) {
        float v = red[0];
        #pragma unroll
        for (int i = 1; i < 8; i++) v = fmaxf(v, red[i]);
        bc = v;
    }
    __syncthreads();
    m = bc;
    __syncthreads();

    float ss = 0.f;
    for (int i = s + tid; i < e; i += 256) ss += expf(g_scores[i] - m);
    #pragma unroll
    for (int off = 16; off; off >>= 1) ss += __shfl_xor_sync(0xffffffffu, ss, off);
    if ((tid & 31) == 0) red[tid >> 5] = ss;
    __syncthreads();
    if (tid == 0) {
        float v = 0.f;
        #pragma unroll
        for (int i = 0; i < 8; i++) v += red[i];
        bc = v;
    }
    __syncthreads();
    const float inv = 1.0f / bc;
    for (int i = s + tid; i < e; i += 256) g_scores[i] = expf(g_scores[i] - m) * inv;
}

// ---------------- pool2: uniform row blocks + per-segment atomic flush ----------------
constexpr int RPB = 512;
constexpr int PBLK = (NROWS + RPB - 1) / RPB;  // 391

__global__ void __launch_bounds__(256)
pool2_kernel(const float *__restrict__ x, const int *__restrict__ batch,
             float *__restrict__ out) {
    const int tid = threadIdx.x;
    const int r0 = blockIdx.x * RPB;
    const int rend = min(r0 + RPB, NROWS);
    const int g0 = batch[r0], g1 = batch[rend - 1];

    for (int g = g0; g <= g1; g++) {
        const int s = max(g_seg[g], r0);
        const int e = min(g_seg[g + 1], rend);
        if (s >= e) continue;
        float a0 = 0.f, a1 = 0.f, a2 = 0.f, a3 = 0.f;
        int r = s;
        for (; r + 4 <= e; r += 4) {
            float x0 = x[(size_t)(r + 0) * DIMX + tid];
            float x1 = x[(size_t)(r + 1) * DIMX + tid];
            float x2 = x[(size_t)(r + 2) * DIMX + tid];
            float x3 = x[(size_t)(r + 3) * DIMX + tid];
            float w0 = g_scores[r + 0], w1 = g_scores[r + 1];
            float w2 = g_scores[r + 2], w3 = g_scores[r + 3];
            a0 = fmaf(w0, x0, a0); a1 = fmaf(w1, x1, a1);
            a2 = fmaf(w2, x2, a2); a3 = fmaf(w3, x3, a3);
        }
        for (; r < e; r++) a0 = fmaf(g_scores[r], x[(size_t)r * DIMX + tid], a0);
        atomicAdd(&out[(size_t)g * DIMX + tid], (a0 + a1) + (a2 + a3));
    }
}

// ---------------- launch ----------------
extern "C" void kernel_launch(void *const *d_in, const int *in_sizes, int n_in,
                              void *d_out, int out_size) {
    (void)in_sizes; (void)n_in; (void)out_size;
    const float *x = (const float *)d_in[0];
    const int *batch = (const int *)d_in[1];
    const float *W1 = (const float *)d_in[2];
    const float *b1 = (const float *)d_in[3];
    const float *W2 = (const float *)d_in[4];
    float *out = (float *)d_out;

    static int grid_s = 0;
    if (grid_s == 0) {
        int sm = 148;
        cudaDeviceGetAttribute(&sm, cudaDevAttrMultiProcessorCount, 0);
        grid_s = sm;
        cudaFuncSetAttribute(scores_kernel, cudaFuncAttributeMaxDynamicSharedMemorySize,
                             SMEM_TOTAL);
    }
    prep_w<<<HID * DIMX / 256, 256>>>(W1);
    prep_cheb<<<1, 64>>>();
    scores_kernel<<<grid_s, TPB, SMEM_TOTAL>>>(x, b1, W2);
    weights_kernel<<<NSEG, 256>>>(batch, out);
    pool2_kernel<<<PBLK, 256>>>(x, batch, out);
}

// round 5
// speedup vs baseline: 1.4887x; 1.1226x over previous
#include <cuda_runtime.h>
#include <cuda_bf16.h>
#include <cstdint>
#include <cstddef>

#define NROWS 200000
#define DIMX 256
#define HID 128
#define NSEG 512

constexpr int TILE_M = 128;
constexpr int NTILES = (NROWS + TILE_M - 1) / TILE_M;  // 1563
constexpr int TPB = 256;  // 8 warps: 4 m-groups x 2 n-groups -> 255-reg cap

#define NCHEB 16
#define NNODE 32
#define CLAMP 4.5f
#define RANGE_T (CLAMP * CLAMP)

// ---- smem layout (bytes) ----
constexpr int SM_B1 = 0;           // float[128]
constexpr int SM_W2 = 512;         // float[128]
constexpr int SM_COEF = 1024;      // float[16]
constexpr int SM_SPART = 1152;     // float[128][2]
constexpr int SM_WHI = 4096;       // 4 panels x 16KB (SW128)
constexpr int SM_WLO = SM_WHI + 65536;
constexpr int SMEM_TOTAL = SM_WLO + 65536;  // 135168

__device__ float g_scores[NROWS];
__device__ int g_seg[NSEG + 1];
__device__ __nv_bfloat16 g_wt_hi[HID * DIMX];  // [n][k]
__device__ __nv_bfloat16 g_wt_lo[HID * DIMX];
__device__ float g_coef[NCHEB];

// ---------------- helpers ----------------
__device__ __forceinline__ uint32_t smem_u32(const void *p) {
    uint32_t a;
    asm("{ .reg .u64 t; cvta.to.shared.u64 t, %1; cvt.u32.u64 %0, t; }" : "=r"(a) : "l"(p));
    return a;
}
#define SWZ(off) ((uint32_t)(off) ^ ((((uint32_t)(off)) >> 3) & 0x70u))

__device__ __forceinline__ uint32_t packbf(float lo, float hi) {
    uint32_t r;
    asm("cvt.rn.bf16x2.f32 %0, %1, %2;" : "=r"(r) : "f"(hi), "f"(lo));
    return r;
}
__device__ __forceinline__ float lo_of(uint32_t p) { return __uint_as_float(p << 16); }
__device__ __forceinline__ float hi_of(uint32_t p) { return __uint_as_float(p & 0xffff0000u); }

__device__ __forceinline__ void ldsm4(uint32_t *r, uint32_t addr) {
    asm volatile("ldmatrix.sync.aligned.m8n8.x4.shared.b16 {%0,%1,%2,%3}, [%4];"
                 : "=r"(r[0]), "=r"(r[1]), "=r"(r[2]), "=r"(r[3]) : "r"(addr));
}
__device__ __forceinline__ void mma16816(float *d, const uint32_t *a, const uint32_t *b) {
    asm volatile("mma.sync.aligned.m16n8k16.row.col.f32.bf16.bf16.f32 "
                 "{%0,%1,%2,%3}, {%4,%5,%6,%7}, {%8,%9}, {%0,%1,%2,%3};"
                 : "+f"(d[0]), "+f"(d[1]), "+f"(d[2]), "+f"(d[3])
                 : "r"(a[0]), "r"(a[1]), "r"(a[2]), "r"(a[3]), "r"(b[0]), "r"(b[1]));
}

// ---------------- prep: W1 -> Wt bf16 hi/lo ----------------
__global__ void prep_w(const float *__restrict__ W1) {
    int i = blockIdx.x * 256 + threadIdx.x;  // 32768
    int k = i >> 7, n = i & 127;             // W1[k][n]
    float v = W1[i];
    __nv_bfloat16 h = __float2bfloat16(v);
    g_wt_hi[n * DIMX + k] = h;
    g_wt_lo[n * DIMX + k] = __float2bfloat16(v - __bfloat162float(h));
}

// ---------------- prep: Chebyshev->monomial coeffs ----------------
__global__ void prep_cheb() {
    __shared__ double cheb[NCHEB], mono[NCHEB];
    int t = threadIdx.x;  // 64 threads
    if (t < NCHEB) { cheb[t] = 0.0; mono[t] = 0.0; }
    __syncthreads();
    if (t < NNODE) {
        double th = 3.14159265358979323846 * (t + 0.5) / NNODE;
        double c1 = cos(th);
        double tt = (double)RANGE_T * 0.5 * (c1 + 1.0);
        double xx = sqrt(tt);
        double g = (xx < 1e-8) ? 1.0 : (tanh(xx) / xx);
        double w = 2.0 / NNODE;
        double Tm = 1.0, Tc = c1;
        atomicAdd(&cheb[0], g * w);
        for (int k = 1; k < NCHEB; k++) {
            atomicAdd(&cheb[k], g * Tc * w);
            double Tn = 2.0 * c1 * Tc - Tm;
            Tm = Tc; Tc = Tn;
        }
    }
    __syncthreads();
    if (t < NCHEB) {
        double ck = cheb[t] * ((t == 0) ? 0.5 : 1.0);
        if (t == 0) {
            atomicAdd(&mono[0], ck);
        } else {
            double fact[NCHEB];
            fact[0] = 1.0;
            for (int i = 1; i < NCHEB; i++) fact[i] = fact[i - 1] * i;
            for (int m = 0; 2 * m <= t; m++) {
                int p = t - 2 * m;
                double p2 = (p >= 1) ? (double)(1ull << (p - 1)) : 0.5;
                double cf = (double)t * fact[t - m - 1] / (fact[m] * fact[p]) * p2;
                if (m & 1) cf = -cf;
                atomicAdd(&mono[p], ck * cf);
            }
        }
    }
    __syncthreads();
    if (t < NCHEB) g_coef[t] = (float)mono[t];
}

__device__ __forceinline__ float ftanh(float x, const float *cf) {
    float xc = fminf(fmaxf(x, -CLAMP), CLAMP);
    float s = fmaf(xc * xc, 2.0f / RANGE_T, -1.0f);
    float p = cf[NCHEB - 1];
    #pragma unroll
    for (int i = NCHEB - 2; i >= 0; i--) p = fmaf(p, s, cf[i]);
    return xc * p;
}

// ---------------- scores: A direct-from-global, sync-free mainloop ----------------
__global__ void __launch_bounds__(TPB, 1)
scores_kernel(const float *__restrict__ x, const float *__restrict__ b1,
              const float *__restrict__ W2) {
    extern __shared__ char smem[];
    const uint32_t sb = smem_u32(smem);
    const int tid = threadIdx.x;
    const int wid = tid >> 5, lane = tid & 31;
    const int mg = wid >> 1, ng = wid & 1;  // rows 32*mg.., cols 64*ng..

    if (tid < HID) {
        ((float *)(smem + SM_B1))[tid] = b1[tid];
        ((float *)(smem + SM_W2))[tid] = W2[tid];
    }
    if (tid < NCHEB) ((float *)(smem + SM_COEF))[tid] = g_coef[tid];
    // stage Wt hi/lo into SW128 panels (panel c: k in [64c, 64c+64))
    for (int i = tid; i < HID * (DIMX / 4); i += TPB) {
        int n = i >> 6, k4 = i & 63;
        uint2 vh = *(const uint2 *)(g_wt_hi + n * DIMX + k4 * 4);
        uint2 vl = *(const uint2 *)(g_wt_lo + n * DIMX + k4 * 4);
        uint32_t off = SWZ(n * 128 + (k4 & 15) * 8) + (uint32_t)(k4 >> 4) * 16384u;
        *(uint2 *)(smem + SM_WHI + off) = vh;
        *(uint2 *)(smem + SM_WLO + off) = vl;
    }
    __syncthreads();

    float *spart = (float *)(smem + SM_SPART);
    const float *b1s = (const float *)(smem + SM_B1);
    const float *w2s = (const float *)(smem + SM_W2);

    const int lr = lane >> 2, cq = lane & 3;
    // B ldsm lane addressing (verified layout)
    const int bn = ng * 64 + ((lane >> 4) & 1) * 8 + (lane & 7);
    const int bkb = ((lane >> 3) & 1) * 8;

    for (int tile = blockIdx.x; tile < NTILES; tile += gridDim.x) {
        const size_t r0 = (size_t)tile * TILE_M;
        const size_t rb = r0 + mg * 32 + lr;
        // clamp pad rows into valid memory; their acc rows are garbage but never stored
        const float2 *p0 = (const float2 *)x + min(rb, (size_t)(NROWS - 1)) * 128;
        const float2 *p1 = (const float2 *)x + min(rb + 8, (size_t)(NROWS - 1)) * 128;
        const float2 *p2 = (const float2 *)x + min(rb + 16, (size_t)(NROWS - 1)) * 128;
        const float2 *p3 = (const float2 *)x + min(rb + 24, (size_t)(NROWS - 1)) * 128;

        // acc init = b1 (folds bias into GEMM)
        float acc[2][8][4];
        #pragma unroll
        for (int mt = 0; mt < 2; mt++)
            #pragma unroll
            for (int nt = 0; nt < 8; nt++) {
                int c0 = ng * 64 + nt * 8 + cq * 2;
                acc[mt][nt][0] = b1s[c0];
                acc[mt][nt][1] = b1s[c0 + 1];
                acc[mt][nt][2] = acc[mt][nt][0];
                acc[mt][nt][3] = acc[mt][nt][1];
            }

        float2 buf[2][8];
        // prologue: load kstep 0
        {
            const int o = cq;
            buf[0][0] = p0[o]; buf[0][1] = p1[o]; buf[0][2] = p0[o + 4]; buf[0][3] = p1[o + 4];
            buf[0][4] = p2[o]; buf[0][5] = p3[o]; buf[0][6] = p2[o + 4]; buf[0][7] = p3[o + 4];
        }

        #pragma unroll 2
        for (int ks = 0; ks < 16; ks++) {
            const int cb = ks & 1;
            if (ks < 15) {
                const int o = (ks + 1) * 8 + cq;
                float2 *nb = buf[cb ^ 1];
                nb[0] = p0[o]; nb[1] = p1[o]; nb[2] = p0[o + 4]; nb[3] = p1[o + 4];
                nb[4] = p2[o]; nb[5] = p3[o]; nb[6] = p2[o + 4]; nb[7] = p3[o + 4];
            }
            // convert A frags
            uint32_t ah[2][4], al[2][4];
            #pragma unroll
            for (int mt = 0; mt < 2; mt++)
                #pragma unroll
                for (int j = 0; j < 4; j++) {
                    float2 v = buf[cb][mt * 4 + j];
                    uint32_t h = packbf(v.x, v.y);
                    ah[mt][j] = h;
                    al[mt][j] = packbf(v.x - lo_of(h), v.y - hi_of(h));
                }
            // ldsm B frags
            uint32_t bh[4][4], bl[4][4];
            const uint32_t whp = sb + SM_WHI + (uint32_t)(ks >> 2) * 16384u;
            const uint32_t wlp = sb + SM_WLO + (uint32_t)(ks >> 2) * 16384u;
            const int ki = (ks & 3) * 16 + bkb;
            #pragma unroll
            for (int nt2 = 0; nt2 < 4; nt2++) {
                uint32_t off = SWZ((bn + nt2 * 16) * 128 + ki * 2);
                ldsm4(bh[nt2], whp + off);
                ldsm4(bl[nt2], wlp + off);
            }
            // 48 HMMA
            #pragma unroll
            for (int mt = 0; mt < 2; mt++)
                #pragma unroll
                for (int nt = 0; nt < 8; nt++) {
                    const uint32_t *bhp = &bh[nt >> 1][(nt & 1) * 2];
                    const uint32_t *blp = &bl[nt >> 1][(nt & 1) * 2];
                    mma16816(acc[mt][nt], ah[mt], bhp);
                    mma16816(acc[mt][nt], ah[mt], blp);
                    mma16816(acc[mt][nt], al[mt], bhp);
                }
        }

        // ---- epilogue: tanh poly + dot W2 (warp-local) ----
        {
            float cf[NCHEB];
            #pragma unroll
            for (int i = 0; i < NCHEB; i++) cf[i] = ((const float *)(smem + SM_COEF))[i];
            #pragma unroll
            for (int mt = 0; mt < 2; mt++)
                #pragma unroll
                for (int qh = 0; qh < 2; qh++) {
                    float p = 0.f;
                    #pragma unroll
                    for (int nt = 0; nt < 8; nt++) {
                        int c0 = ng * 64 + nt * 8 + cq * 2;
                        p += ftanh(acc[mt][nt][qh * 2 + 0], cf) * w2s[c0] +
                             ftanh(acc[mt][nt][qh * 2 + 1], cf) * w2s[c0 + 1];
                    }
                    p += __shfl_xor_sync(0xffffffffu, p, 1);
                    p += __shfl_xor_sync(0xffffffffu, p, 2);
                    if (cq == 0)
                        spart[(mg * 32 + mt * 16 + qh * 8 + lr) * 2 + ng] = p;
                }
        }
        __syncthreads();
        if (tid < 128) {
            size_t row = r0 + tid;
            if (row < NROWS) g_scores[row] = spart[tid * 2] + spart[tid * 2 + 1];
        }
        __syncthreads();
    }
}

// ---------------- weights: per-segment softmax, publish g_seg, zero out ----------------
__device__ __forceinline__ int lbound(const int *__restrict__ b, int target) {
    int lo = 0, hi = NROWS;
    while (lo < hi) {
        int mid = (lo + hi) >> 1;
        if (b[mid] < target) lo = mid + 1;
        else hi = mid;
    }
    return lo;
}

__global__ void __launch_bounds__(256)
weights_kernel(const int *__restrict__ batch, float *__restrict__ out) {
    const int g = blockIdx.x, tid = threadIdx.x;
    __shared__ int sse[2];
    __shared__ float red[8];
    __shared__ float bc;

    if (tid == 0) sse[0] = lbound(batch, g);
    if (tid == 32) sse[1] = lbound(batch, g + 1);
    out[(size_t)g * DIMX + tid] = 0.0f;
    __syncthreads();
    const int s = sse[0], e = sse[1];
    if (tid == 0) {
        g_seg[g] = s;
        if (g == NSEG - 1) g_seg[NSEG] = NROWS;
    }

    float m = -3.4e38f;
    for (int i = s + tid; i < e; i += 256) m = fmaxf(m, g_scores[i]);
    #pragma unroll
    for (int off = 16; off; off >>= 1) m = fmaxf(m, __shfl_xor_sync(0xffffffffu, m, off));
    if ((tid & 31) == 0) red[tid >> 5] = m;
    __syncthreads();
    if (tid == 0) {
        float v = red[0];
        #pragma unroll
        for (int i = 1; i < 8; i++) v = fmaxf(v, red[i]);
        bc = v;
    }
    __syncthreads();
    m = bc;
    __syncthreads();

    float ss = 0.f;
    for (int i = s + tid; i < e; i += 256) ss += expf(g_scores[i] - m);
    #pragma unroll
    for (int off = 16; off; off >>= 1) ss += __shfl_xor_sync(0xffffffffu, ss, off);
    if ((tid & 31) == 0) red[tid >> 5] = ss;
    __syncthreads();
    if (tid == 0) {
        float v = 0.f;
        #pragma unroll
        for (int i = 0; i < 8; i++) v += red[i];
        bc = v;
    }
    __syncthreads();
    const float inv = 1.0f / bc;
    for (int i = s + tid; i < e; i += 256) g_scores[i] = expf(g_scores[i] - m) * inv;
}

// ---------------- pool2: uniform row blocks + per-segment atomic flush ----------------
constexpr int RPB = 256;
constexpr int PBLK = (NROWS + RPB - 1) / RPB;  // 782

__global__ void __launch_bounds__(256)
pool2_kernel(const float *__restrict__ x, const int *__restrict__ batch,
             float *__restrict__ out) {
    const int tid = threadIdx.x;
    const int r0 = blockIdx.x * RPB;
    const int rend = min(r0 + RPB, NROWS);
    const int g0 = batch[r0], g1 = batch[rend - 1];

    for (int g = g0; g <= g1; g++) {
        const int s = max(g_seg[g], r0);
        const int e = min(g_seg[g + 1], rend);
        if (s >= e) continue;
        float a0 = 0.f, a1 = 0.f, a2 = 0.f, a3 = 0.f;
        float a4 = 0.f, a5 = 0.f, a6 = 0.f, a7 = 0.f;
        int r = s;
        for (; r + 8 <= e; r += 8) {
            a0 = fmaf(g_scores[r + 0], x[(size_t)(r + 0) * DIMX + tid], a0);
            a1 = fmaf(g_scores[r + 1], x[(size_t)(r + 1) * DIMX + tid], a1);
            a2 = fmaf(g_scores[r + 2], x[(size_t)(r + 2) * DIMX + tid], a2);
            a3 = fmaf(g_scores[r + 3], x[(size_t)(r + 3) * DIMX + tid], a3);
            a4 = fmaf(g_scores[r + 4], x[(size_t)(r + 4) * DIMX + tid], a4);
            a5 = fmaf(g_scores[r + 5], x[(size_t)(r + 5) * DIMX + tid], a5);
            a6 = fmaf(g_scores[r + 6], x[(size_t)(r + 6) * DIMX + tid], a6);
            a7 = fmaf(g_scores[r + 7], x[(size_t)(r + 7) * DIMX + tid], a7);
        }
        for (; r < e; r++) a0 = fmaf(g_scores[r], x[(size_t)r * DIMX + tid], a0);
        atomicAdd(&out[(size_t)g * DIMX + tid],
                  ((a0 + a1) + (a2 + a3)) + ((a4 + a5) + (a6 + a7)));
    }
}

// ---------------- launch ----------------
extern "C" void kernel_launch(void *const *d_in, const int *in_sizes, int n_in,
                              void *d_out, int out_size) {
    (void)in_sizes; (void)n_in; (void)out_size;
    const float *x = (const float *)d_in[0];
    const int *batch = (const int *)d_in[1];
    const float *W1 = (const float *)d_in[2];
    const float *b1 = (const float *)d_in[3];
    const float *W2 = (const float *)d_in[4];
    float *out = (float *)d_out;

    static int grid_s = 0;
    if (grid_s == 0) {
        int sm = 148;
        cudaDeviceGetAttribute(&sm, cudaDevAttrMultiProcessorCount, 0);
        grid_s = sm;
        cudaFuncSetAttribute(scores_kernel, cudaFuncAttributeMaxDynamicSharedMemorySize,
                             SMEM_TOTAL);
    }
    prep_w<<<HID * DIMX / 256, 256>>>(W1);
    prep_cheb<<<1, 64>>>();
    scores_kernel<<<grid_s, TPB, SMEM_TOTAL>>>(x, b1, W2);
    weights_kernel<<<NSEG, 256>>>(batch, out);
    pool2_kernel<<<PBLK, 256>>>(x, batch, out);
}

// round 6
// speedup vs baseline: 1.5876x; 1.0664x over previous
#include <cuda_runtime.h>
#include <cuda_fp16.h>
#include <cstdint>
#include <cstddef>

#define NROWS 200000
#define DIMX 256
#define HID 128
#define NSEG 512

constexpr int TILE_M = 128;
constexpr int NTILES = (NROWS + TILE_M - 1) / TILE_M;  // 1563
constexpr int TPB = 256;  // 8 warps: 4 m-groups x 2 n-groups

#define NCHEB 16
#define NNODE 32
#define CLAMP 4.5f
#define RANGE_T (CLAMP * CLAMP)

// ---- smem layout (bytes) ----
constexpr int SM_B1 = 0;           // float[128]
constexpr int SM_W2 = 512;         // float[128]
constexpr int SM_COEF = 1024;      // float[16]
constexpr int SM_SPART = 1152;     // float[128][2]
constexpr int SM_WHI = 4096;       // 4 panels x 16KB (SW128, fp16)
constexpr int SM_WLO = SM_WHI + 65536;
constexpr int SMEM_TOTAL = SM_WLO + 65536;  // 135168

__device__ float g_scores[NROWS];
__device__ int g_seg[NSEG + 1];
__device__ __half g_wt_hi[HID * DIMX];  // [n][k]
__device__ __half g_wt_lo[HID * DIMX];
__device__ float g_coef[NCHEB];

// ---------------- helpers ----------------
__device__ __forceinline__ uint32_t smem_u32(const void *p) {
    uint32_t a;
    asm("{ .reg .u64 t; cvta.to.shared.u64 t, %1; cvt.u32.u64 %0, t; }" : "=r"(a) : "l"(p));
    return a;
}
#define SWZ(off) ((uint32_t)(off) ^ ((((uint32_t)(off)) >> 3) & 0x70u))

// pack two fp32 -> f16x2 (hi arg -> upper half, matching bf16x2 convention verified earlier)
__device__ __forceinline__ uint32_t packh(float lo, float hi) {
    uint32_t r;
    asm("cvt.rn.f16x2.f32 %0, %1, %2;" : "=r"(r) : "f"(hi), "f"(lo));
    return r;
}

__device__ __forceinline__ void ldsm4(uint32_t *r, uint32_t addr) {
    asm volatile("ldmatrix.sync.aligned.m8n8.x4.shared.b16 {%0,%1,%2,%3}, [%4];"
                 : "=r"(r[0]), "=r"(r[1]), "=r"(r[2]), "=r"(r[3]) : "r"(addr));
}
__device__ __forceinline__ void mma16816(float *d, const uint32_t *a, const uint32_t *b) {
    asm volatile("mma.sync.aligned.m16n8k16.row.col.f32.f16.f16.f32 "
                 "{%0,%1,%2,%3}, {%4,%5,%6,%7}, {%8,%9}, {%0,%1,%2,%3};"
                 : "+f"(d[0]), "+f"(d[1]), "+f"(d[2]), "+f"(d[3])
                 : "r"(a[0]), "r"(a[1]), "r"(a[2]), "r"(a[3]), "r"(b[0]), "r"(b[1]));
}

// ---------------- prep: W1 -> Wt fp16 hi/lo ----------------
__global__ void prep_w(const float *__restrict__ W1) {
    int i = blockIdx.x * 256 + threadIdx.x;  // 32768
    int k = i >> 7, n = i & 127;             // W1[k][n]
    float v = W1[i];
    __half h = __float2half_rn(v);
    g_wt_hi[n * DIMX + k] = h;
    g_wt_lo[n * DIMX + k] = __float2half_rn(v - __half2float(h));
}

// ---------------- prep: Chebyshev->monomial coeffs of tanh(sqrt(t))/sqrt(t) ----------------
__global__ void prep_cheb() {
    __shared__ double cheb[NCHEB], mono[NCHEB];
    int t = threadIdx.x;  // 64 threads
    if (t < NCHEB) { cheb[t] = 0.0; mono[t] = 0.0; }
    __syncthreads();
    if (t < NNODE) {
        double th = 3.14159265358979323846 * (t + 0.5) / NNODE;
        double c1 = cos(th);
        double tt = (double)RANGE_T * 0.5 * (c1 + 1.0);
        double xx = sqrt(tt);
        double g = (xx < 1e-8) ? 1.0 : (tanh(xx) / xx);
        double w = 2.0 / NNODE;
        double Tm = 1.0, Tc = c1;
        atomicAdd(&cheb[0], g * w);
        for (int k = 1; k < NCHEB; k++) {
            atomicAdd(&cheb[k], g * Tc * w);
            double Tn = 2.0 * c1 * Tc - Tm;
            Tm = Tc; Tc = Tn;
        }
    }
    __syncthreads();
    if (t < NCHEB) {
        double ck = cheb[t] * ((t == 0) ? 0.5 : 1.0);
        if (t == 0) {
            atomicAdd(&mono[0], ck);
        } else {
            double fact[NCHEB];
            fact[0] = 1.0;
            for (int i = 1; i < NCHEB; i++) fact[i] = fact[i - 1] * i;
            for (int m = 0; 2 * m <= t; m++) {
                int p = t - 2 * m;
                double p2 = (p >= 1) ? (double)(1ull << (p - 1)) : 0.5;
                double cf = (double)t * fact[t - m - 1] / (fact[m] * fact[p]) * p2;
                if (m & 1) cf = -cf;
                atomicAdd(&mono[p], ck * cf);
            }
        }
    }
    __syncthreads();
    if (t < NCHEB) g_coef[t] = (float)mono[t];
}

__device__ __forceinline__ float ftanh(float x, const float *cf) {
    float xc = fminf(fmaxf(x, -CLAMP), CLAMP);
    float s = fmaf(xc * xc, 2.0f / RANGE_T, -1.0f);
    float p = cf[NCHEB - 1];
    #pragma unroll
    for (int i = NCHEB - 2; i >= 0; i--) p = fmaf(p, s, cf[i]);
    return xc * p;
}

// ---------------- scores: fp16 2-term, A direct-from-global, sync-free mainloop ----------------
__global__ void __launch_bounds__(TPB, 1)
scores_kernel(const float *__restrict__ x, const float *__restrict__ b1,
              const float *__restrict__ W2) {
    extern __shared__ char smem[];
    const uint32_t sb = smem_u32(smem);
    const int tid = threadIdx.x;
    const int wid = tid >> 5, lane = tid & 31;
    const int mg = wid >> 1, ng = wid & 1;  // rows 32*mg.., cols 64*ng..

    if (tid < HID) {
        ((float *)(smem + SM_B1))[tid] = b1[tid];
        ((float *)(smem + SM_W2))[tid] = W2[tid];
    }
    if (tid < NCHEB) ((float *)(smem + SM_COEF))[tid] = g_coef[tid];
    // stage Wt hi/lo into SW128 panels (panel c: k in [64c, 64c+64))
    for (int i = tid; i < HID * (DIMX / 4); i += TPB) {
        int n = i >> 6, k4 = i & 63;
        uint2 vh = *(const uint2 *)(g_wt_hi + n * DIMX + k4 * 4);
        uint2 vl = *(const uint2 *)(g_wt_lo + n * DIMX + k4 * 4);
        uint32_t off = SWZ(n * 128 + (k4 & 15) * 8) + (uint32_t)(k4 >> 4) * 16384u;
        *(uint2 *)(smem + SM_WHI + off) = vh;
        *(uint2 *)(smem + SM_WLO + off) = vl;
    }
    __syncthreads();

    float *spart = (float *)(smem + SM_SPART);
    const float *b1s = (const float *)(smem + SM_B1);
    const float *w2s = (const float *)(smem + SM_W2);

    const int lr = lane >> 2, cq = lane & 3;
    const int bn = ng * 64 + ((lane >> 4) & 1) * 8 + (lane & 7);
    const int bkb = ((lane >> 3) & 1) * 8;

    for (int tile = blockIdx.x; tile < NTILES; tile += gridDim.x) {
        const size_t r0 = (size_t)tile * TILE_M;
        const size_t rb = r0 + mg * 32 + lr;
        // clamp pad rows into valid memory; their acc rows are garbage but never stored
        const float2 *p0 = (const float2 *)x + min(rb, (size_t)(NROWS - 1)) * 128;
        const float2 *p1 = (const float2 *)x + min(rb + 8, (size_t)(NROWS - 1)) * 128;
        const float2 *p2 = (const float2 *)x + min(rb + 16, (size_t)(NROWS - 1)) * 128;
        const float2 *p3 = (const float2 *)x + min(rb + 24, (size_t)(NROWS - 1)) * 128;

        // acc init = b1 (bias folded)
        float acc[2][8][4];
        #pragma unroll
        for (int mt = 0; mt < 2; mt++)
            #pragma unroll
            for (int nt = 0; nt < 8; nt++) {
                int c0 = ng * 64 + nt * 8 + cq * 2;
                acc[mt][nt][0] = b1s[c0];
                acc[mt][nt][1] = b1s[c0 + 1];
                acc[mt][nt][2] = acc[mt][nt][0];
                acc[mt][nt][3] = acc[mt][nt][1];
            }

        float2 buf[2][8];
        {
            const int o = cq;
            buf[0][0] = p0[o]; buf[0][1] = p1[o]; buf[0][2] = p0[o + 4]; buf[0][3] = p1[o + 4];
            buf[0][4] = p2[o]; buf[0][5] = p3[o]; buf[0][6] = p2[o + 4]; buf[0][7] = p3[o + 4];
        }

        #pragma unroll 2
        for (int ks = 0; ks < 16; ks++) {
            const int cb = ks & 1;
            if (ks < 15) {
                const int o = (ks + 1) * 8 + cq;
                float2 *nb = buf[cb ^ 1];
                nb[0] = p0[o]; nb[1] = p1[o]; nb[2] = p0[o + 4]; nb[3] = p1[o + 4];
                nb[4] = p2[o]; nb[5] = p3[o]; nb[6] = p2[o + 4]; nb[7] = p3[o + 4];
            }
            // convert A frags: single fp16 (8 cvt)
            uint32_t ah[2][4];
            #pragma unroll
            for (int mt = 0; mt < 2; mt++)
                #pragma unroll
                for (int j = 0; j < 4; j++) {
                    float2 v = buf[cb][mt * 4 + j];
                    ah[mt][j] = packh(v.x, v.y);
                }
            // ldsm B frags (hi + lo panels)
            uint32_t bh[4][4], bl[4][4];
            const uint32_t whp = sb + SM_WHI + (uint32_t)(ks >> 2) * 16384u;
            const uint32_t wlp = sb + SM_WLO + (uint32_t)(ks >> 2) * 16384u;
            const int ki = (ks & 3) * 16 + bkb;
            #pragma unroll
            for (int nt2 = 0; nt2 < 4; nt2++) {
                uint32_t off = SWZ((bn + nt2 * 16) * 128 + ki * 2);
                ldsm4(bh[nt2], whp + off);
                ldsm4(bl[nt2], wlp + off);
            }
            // 32 HMMA: ah*(wh) + ah*(wl)
            #pragma unroll
            for (int mt = 0; mt < 2; mt++)
                #pragma unroll
                for (int nt = 0; nt < 8; nt++) {
                    const uint32_t *bhp = &bh[nt >> 1][(nt & 1) * 2];
                    const uint32_t *blp = &bl[nt >> 1][(nt & 1) * 2];
                    mma16816(acc[mt][nt], ah[mt], bhp);
                    mma16816(acc[mt][nt], ah[mt], blp);
                }
        }

        // ---- epilogue: tanh poly + dot W2 ----
        {
            float cf[NCHEB];
            #pragma unroll
            for (int i = 0; i < NCHEB; i++) cf[i] = ((const float *)(smem + SM_COEF))[i];
            #pragma unroll
            for (int mt = 0; mt < 2; mt++)
                #pragma unroll
                for (int qh = 0; qh < 2; qh++) {
                    float p = 0.f;
                    #pragma unroll
                    for (int nt = 0; nt < 8; nt++) {
                        int c0 = ng * 64 + nt * 8 + cq * 2;
                        p += ftanh(acc[mt][nt][qh * 2 + 0], cf) * w2s[c0] +
                             ftanh(acc[mt][nt][qh * 2 + 1], cf) * w2s[c0 + 1];
                    }
                    p += __shfl_xor_sync(0xffffffffu, p, 1);
                    p += __shfl_xor_sync(0xffffffffu, p, 2);
                    if (cq == 0)
                        spart[(mg * 32 + mt * 16 + qh * 8 + lr) * 2 + ng] = p;
                }
        }
        __syncthreads();
        if (tid < 128) {
            size_t row = r0 + tid;
            if (row < NROWS) g_scores[row] = spart[tid * 2] + spart[tid * 2 + 1];
        }
        __syncthreads();
    }
}

// ---------------- weights: one warp per segment, no block barriers ----------------
__device__ __forceinline__ int lbound(const int *__restrict__ b, int target) {
    int lo = 0, hi = NROWS;
    while (lo < hi) {
        int mid = (lo + hi) >> 1;
        if (b[mid] < target) lo = mid + 1;
        else hi = mid;
    }
    return lo;
}

__global__ void __launch_bounds__(128)
weights_kernel(const int *__restrict__ batch, float *__restrict__ out) {
    const int w = blockIdx.x * 4 + (threadIdx.x >> 5);  // segment id, 512 warps
    const int lane = threadIdx.x & 31;
    if (w >= NSEG) return;

    int s = lbound(batch, w);          // each lane computes (identical) — cheap, cached
    int e = lbound(batch, w + 1);
    if (lane == 0) {
        g_seg[w] = s;
        if (w == NSEG - 1) g_seg[NSEG] = NROWS;
    }
    // zero out row
    float4 *orow = (float4 *)(out + (size_t)w * DIMX);
    #pragma unroll
    for (int i = lane; i < 64; i += 32) orow[i] = make_float4(0.f, 0.f, 0.f, 0.f);

    float m = -3.4e38f;
    for (int i = s + lane; i < e; i += 32) m = fmaxf(m, g_scores[i]);
    #pragma unroll
    for (int off = 16; off; off >>= 1) m = fmaxf(m, __shfl_xor_sync(0xffffffffu, m, off));

    float ss = 0.f;
    for (int i = s + lane; i < e; i += 32) ss += expf(g_scores[i] - m);
    #pragma unroll
    for (int off = 16; off; off >>= 1) ss += __shfl_xor_sync(0xffffffffu, ss, off);

    const float inv = 1.0f / ss;
    for (int i = s + lane; i < e; i += 32) g_scores[i] = expf(g_scores[i] - m) * inv;
}

// ---------------- pool2: uniform row blocks + per-segment atomic flush ----------------
constexpr int RPB = 256;
constexpr int PBLK = (NROWS + RPB - 1) / RPB;  // 782

__global__ void __launch_bounds__(256)
pool2_kernel(const float *__restrict__ x, const int *__restrict__ batch,
             float *__restrict__ out) {
    const int tid = threadIdx.x;
    const int r0 = blockIdx.x * RPB;
    const int rend = min(r0 + RPB, NROWS);
    const int g0 = batch[r0], g1 = batch[rend - 1];

    for (int g = g0; g <= g1; g++) {
        const int s = max(g_seg[g], r0);
        const int e = min(g_seg[g + 1], rend);
        if (s >= e) continue;
        float a0 = 0.f, a1 = 0.f, a2 = 0.f, a3 = 0.f;
        float a4 = 0.f, a5 = 0.f, a6 = 0.f, a7 = 0.f;
        int r = s;
        for (; r + 8 <= e; r += 8) {
            a0 = fmaf(g_scores[r + 0], x[(size_t)(r + 0) * DIMX + tid], a0);
            a1 = fmaf(g_scores[r + 1], x[(size_t)(r + 1) * DIMX + tid], a1);
            a2 = fmaf(g_scores[r + 2], x[(size_t)(r + 2) * DIMX + tid], a2);
            a3 = fmaf(g_scores[r + 3], x[(size_t)(r + 3) * DIMX + tid], a3);
            a4 = fmaf(g_scores[r + 4], x[(size_t)(r + 4) * DIMX + tid], a4);
            a5 = fmaf(g_scores[r + 5], x[(size_t)(r + 5) * DIMX + tid], a5);
            a6 = fmaf(g_scores[r + 6], x[(size_t)(r + 6) * DIMX + tid], a6);
            a7 = fmaf(g_scores[r + 7], x[(size_t)(r + 7) * DIMX + tid], a7);
        }
        for (; r < e; r++) a0 = fmaf(g_scores[r], x[(size_t)r * DIMX + tid], a0);
        atomicAdd(&out[(size_t)g * DIMX + tid],
                  ((a0 + a1) + (a2 + a3)) + ((a4 + a5) + (a6 + a7)));
    }
}

// ---------------- launch ----------------
extern "C" void kernel_launch(void *const *d_in, const int *in_sizes, int n_in,
                              void *d_out, int out_size) {
    (void)in_sizes; (void)n_in; (void)out_size;
    const float *x = (const float *)d_in[0];
    const int *batch = (const int *)d_in[1];
    const float *W1 = (const float *)d_in[2];
    const float *b1 = (const float *)d_in[3];
    const float *W2 = (const float *)d_in[4];
    float *out = (float *)d_out;

    static int grid_s = 0;
    if (grid_s == 0) {
        int sm = 148;
        cudaDeviceGetAttribute(&sm, cudaDevAttrMultiProcessorCount, 0);
        grid_s = sm;
        cudaFuncSetAttribute(scores_kernel, cudaFuncAttributeMaxDynamicSharedMemorySize,
                             SMEM_TOTAL);
    }
    prep_w<<<HID * DIMX / 256, 256>>>(W1);
    prep_cheb<<<1, 64>>>();
    scores_kernel<<<grid_s, TPB, SMEM_TOTAL>>>(x, b1, W2);
    weights_kernel<<<(NSEG + 3) / 4, 128>>>(batch, out);
    pool2_kernel<<<PBLK, 256>>>(x, batch, out);
}